// round 12
// baseline (speedup 1.0000x reference)
#include <cuda_runtime.h>
#include <cuda_bf16.h>
#include <cstdint>

// Problem constants
static constexpr int BATCH = 8;
static constexpr int SEQ   = 2048;
static constexpr int DIM   = 768;
static constexpr long long BSD = (long long)BATCH * SEQ * DIM;

// Scratch (device globals: allocation-free per harness rules). 16B-aligned for cp.async.
__device__ __align__(16) float g_xtf[BATCH * SEQ * DIM];      // x, tf32-rounded
__device__ __align__(16) float g_wt[3 * DIM * DIM];           // W^T per slice, tf32-rounded
__device__ __align__(16) float g_qkv[3 * BATCH * SEQ * DIM];  // q|k|v (tf32-rounded)
__device__ __align__(16) float g_s[BATCH * SEQ * SEQ];        // scores / attn

__device__ __forceinline__ uint32_t f2tf32(float f) {
    uint32_t u;
    asm volatile("cvt.rna.tf32.f32 %0, %1;" : "=r"(u) : "f"(f));
    return u;
}
__device__ __forceinline__ float rna(float f) { return __uint_as_float(f2tf32(f)); }

__device__ __forceinline__ void mma_tf32(
    float& c0, float& c1, float& c2, float& c3,
    uint32_t a0, uint32_t a1, uint32_t a2, uint32_t a3,
    uint32_t b0, uint32_t b1)
{
    asm volatile(
        "mma.sync.aligned.m16n8k8.row.col.f32.tf32.tf32.f32 "
        "{%0,%1,%2,%3}, {%4,%5,%6,%7}, {%8,%9}, {%0,%1,%2,%3};\n"
        : "+f"(c0), "+f"(c1), "+f"(c2), "+f"(c3)
        : "r"(a0), "r"(a1), "r"(a2), "r"(a3), "r"(b0), "r"(b1));
}

__device__ __forceinline__ void ldmx4(uint32_t& r0, uint32_t& r1, uint32_t& r2, uint32_t& r3,
                                      uint32_t saddr)
{
    asm volatile("ldmatrix.sync.aligned.m8n8.x4.shared.b16 {%0,%1,%2,%3}, [%4];"
                 : "=r"(r0), "=r"(r1), "=r"(r2), "=r"(r3) : "r"(saddr));
}

__device__ __forceinline__ void cp16(void* smem_dst, const void* gsrc) {
    uint32_t sa = (uint32_t)__cvta_generic_to_shared(smem_dst);
    asm volatile("cp.async.cg.shared.global [%0], [%1], 16;\n" :: "r"(sa), "l"(gsrc));
}

// ---- mbarrier helpers ----
__device__ __forceinline__ void mbar_init(uint32_t a, uint32_t cnt) {
    asm volatile("mbarrier.init.shared.b64 [%0], %1;" :: "r"(a), "r"(cnt) : "memory");
}
__device__ __forceinline__ void mbar_arrive(uint32_t a) {
    asm volatile("mbarrier.arrive.shared.b64 _, [%0];" :: "r"(a) : "memory");
}
__device__ __forceinline__ void cpasync_mbar_arrive(uint32_t a) {
    asm volatile("cp.async.mbarrier.arrive.noinc.shared.b64 [%0];" :: "r"(a) : "memory");
}
__device__ __forceinline__ void mbar_wait(uint32_t a, uint32_t parity) {
    asm volatile(
        "{\n\t.reg .pred P;\n"
        "WL_%=:\n\t"
        "mbarrier.try_wait.parity.acquire.cta.shared::cta.b64 P, [%0], %1, 0x989680;\n\t"
        "@P bra.uni WD_%=;\n\t"
        "bra.uni WL_%=;\n"
        "WD_%=:\n\t}"
        :: "r"(a), "r"(parity) : "memory");
}

// ---------------------------------------------------------------------------
// tf32 tensor-core GEMM, 3-stage cp.async pipeline with PER-STAGE MBARRIERS.
// C = alpha * A @ B(^T); inputs already tf32-rounded.
//   A: [M,K] row-major; B: NT (BT=true) -> [N,K]; NN -> [K,N]; C: [M,N]
// R12: CTA tile 256x128x32, 512 threads / 16 warps (4m x 4n), warp tile
// 64x32 unchanged. Same per-SM output as 2x(128x128) CTAs but smem traffic
// per round drops 288KB -> 240KB (A-tile shared across twice the M).
// Viable at 1 CTA/SM because R11's mbarrier ring has NO block-wide barrier
// in the loop (R7's lockstep failure mode is gone).
//   As [m][k] s36 ; BsNT [n][k] s36 ; BsNN [k][n] s136
// full[s]: 512 cp.async arrivals; empty[s]: 16 per-warp arrivals.
// ---------------------------------------------------------------------------
#define BM 256
#define BN 128
#define BK 32
#define NTHREADS 512
#define NWARPS 16
#define STAGES 3

static constexpr int AS_STRIDE = BK + 4;                 // 36
static constexpr int ASZ = BM * AS_STRIDE;               // 9216 floats per A stage
static constexpr int MBAR_FLOATS = 32;                   // 128 B for 3x(full,empty)
template <bool BT> struct BDims {
    static constexpr int STRIDE = BT ? (BK + 4) : (BN + 8);
    static constexpr int SZ     = BT ? (BN * (BK + 4)) : (BK * (BN + 8));
};

template <bool BT, bool ROUND>
__global__ __launch_bounds__(NTHREADS, 1) void mma_gemm(
    const float* __restrict__ Ab, const float* __restrict__ Bb,
    float* __restrict__ Cb,
    int M, int N, int K,
    long long sA, long long sB, long long sC, float alpha)
{
    constexpr int BS_STRIDE = BDims<BT>::STRIDE;
    constexpr int BSZ       = BDims<BT>::SZ;

    const float* A = Ab + (long long)blockIdx.z * sA;
    const float* B = Bb + (long long)blockIdx.z * sB;
    float*       C = Cb + (long long)blockIdx.z * sC;

    extern __shared__ float smem[];
    const uint32_t mb = (uint32_t)__cvta_generic_to_shared(smem);  // mbar area
    float* AsBase = smem + MBAR_FLOATS;
    float* BsBase = AsBase + STAGES * ASZ;

    const int tid  = threadIdx.x;
    const int warp = tid >> 5;
    const int lane = tid & 31;
    const int gid  = lane >> 2;   // 0..7
    const int tig  = lane & 3;    // 0..3
    const int wm   = (warp >> 2) * 64;   // 0,64,128,192
    const int wn   = (warp & 3) * 32;    // 0,32,64,96
    const int row0 = blockIdx.y * BM;
    const int col0 = blockIdx.x * BN;

    // mbarrier addresses: full[s] = mb + s*16, empty[s] = mb + s*16 + 8
    if (tid == 0) {
#pragma unroll
        for (int s = 0; s < STAGES; s++) {
            mbar_init(mb + s * 16, NTHREADS);   // full: one cp.async arrive per thread
            mbar_init(mb + s * 16 + 8, NWARPS); // empty: one arrive per warp
        }
    }
    __syncthreads();
    // Pre-arm empties: phase 0 completes -> producers may fill.
    if (lane == 0) {
#pragma unroll
        for (int s = 0; s < STAGES; s++) mbar_arrive(mb + s * 16 + 8);
    }

    // ldmatrix per-lane byte offsets (verified R10/R11)
    const uint32_t laneAOff = (uint32_t)((lane & 15) * AS_STRIDE * 4 + (lane & 16));
    const uint32_t laneBOff = (uint32_t)(((lane & 7) + ((lane & 16) >> 1)) * BS_STRIDE * 4
                                         + (lane & 8) * 2);

    float c[4][4][4];
#pragma unroll
    for (int i = 0; i < 4; i++)
#pragma unroll
        for (int j = 0; j < 4; j++)
#pragma unroll
            for (int r = 0; r < 4; r++) c[i][j][r] = 0.f;

    // Loader indices (512 threads)
    const int aR = tid >> 3;            // 0..63 (+64/pass), 16B along k
    const int aC = (tid & 7) * 4;
    const int bR = tid >> 5;            // 0..15 (+16/pass), 16B along n (NN)
    const int bC = (tid & 31) * 4;

    auto load_tile = [&](int stage, int kt) {
        float* As = AsBase + stage * ASZ;
        float* Bs = BsBase + stage * BSZ;
#pragma unroll
        for (int p = 0; p < 4; p++) {       // A: 256 rows
            int r = aR + p * 64;
            cp16(&As[r * AS_STRIDE + aC], A + (long long)(row0 + r) * K + kt + aC);
        }
        if (BT) {
#pragma unroll
            for (int p = 0; p < 2; p++) {   // B NT: 128 rows
                int r = aR + p * 64;
                cp16(&Bs[r * BS_STRIDE + aC], B + (long long)(col0 + r) * K + kt + aC);
            }
        } else {
#pragma unroll
            for (int p = 0; p < 2; p++) {   // B NN: 32 rows x 128 cols
                int r = bR + p * 16;
                cp16(&Bs[r * BS_STRIDE + bC], B + (long long)(kt + r) * N + col0 + bC);
            }
        }
    };

    const int T = K / BK;

    // Producer cursor (per thread)
    int ps = 0, pp = 0;
#pragma unroll
    for (int i = 0; i < STAGES; i++) {
        if (i < T) {
            mbar_wait(mb + ps * 16 + 8, pp);
            load_tile(ps, i * BK);
            cpasync_mbar_arrive(mb + ps * 16);
            if (++ps == STAGES) { ps = 0; pp ^= 1; }
        }
    }

    // Consumer cursor (per warp)
    int cs = 0, cph = 0;
    for (int t = 0; t < T; t++) {
        mbar_wait(mb + cs * 16, cph);   // stage cs tile ready (acquire)

        float* AsF = AsBase + cs * ASZ;
        float* BsF = BsBase + cs * BSZ;
        const uint32_t asAddr = (uint32_t)__cvta_generic_to_shared(AsF) + laneAOff;
        const uint32_t bsAddrNT = (uint32_t)__cvta_generic_to_shared(BsF) + laneBOff;
        const uint32_t* Bs = (const uint32_t*)BsF;

#pragma unroll
        for (int ks = 0; ks < BK; ks += 8) {
            uint32_t a[4][4];
#pragma unroll
            for (int i = 0; i < 4; i++)
                ldmx4(a[i][0], a[i][1], a[i][2], a[i][3],
                      asAddr + (uint32_t)(((wm + 16 * i) * AS_STRIDE + ks) * 4));
            uint32_t b[4][2];
            if (BT) {
#pragma unroll
                for (int jp = 0; jp < 2; jp++)
                    ldmx4(b[2 * jp][0], b[2 * jp][1], b[2 * jp + 1][0], b[2 * jp + 1][1],
                          bsAddrNT + (uint32_t)(((wn + 16 * jp) * BS_STRIDE + ks) * 4));
            } else {
#pragma unroll
                for (int j = 0; j < 4; j++) {
                    int n = wn + 8 * j + gid;
                    b[j][0] = Bs[(ks + tig) * BS_STRIDE + n];
                    b[j][1] = Bs[(ks + tig + 4) * BS_STRIDE + n];
                }
            }
#pragma unroll
            for (int i = 0; i < 4; i++)
#pragma unroll
                for (int j = 0; j < 4; j++)
                    mma_tf32(c[i][j][0], c[i][j][1], c[i][j][2], c[i][j][3],
                             a[i][0], a[i][1], a[i][2], a[i][3],
                             b[j][0], b[j][1]);
        }

        // This warp is done reading stage cs.
        if (lane == 0) mbar_arrive(mb + cs * 16 + 8);
        if (++cs == STAGES) { cs = 0; cph ^= 1; }

        // Produce tile t+STAGES into the stage being freed.
        int nt = t + STAGES;
        if (nt < T) {
            mbar_wait(mb + ps * 16 + 8, pp);   // all warps done with that stage
            load_tile(ps, nt * BK);
            cpasync_mbar_arrive(mb + ps * 16);
            if (++ps == STAGES) { ps = 0; pp ^= 1; }
        }
    }

#pragma unroll
    for (int i = 0; i < 4; i++) {
        int rowA = row0 + wm + 16 * i + gid;
#pragma unroll
        for (int j = 0; j < 4; j++) {
            int col = col0 + wn + 8 * j + 2 * tig;
            float f0 = c[i][j][0] * alpha, f1 = c[i][j][1] * alpha;
            float f2 = c[i][j][2] * alpha, f3 = c[i][j][3] * alpha;
            if (ROUND) { f0 = rna(f0); f1 = rna(f1); f2 = rna(f2); f3 = rna(f3); }
            *(float2*)(C + (long long)rowA * N + col) = make_float2(f0, f1);
            *(float2*)(C + (long long)(rowA + 8) * N + col) = make_float2(f2, f3);
        }
    }
}

// ---------------------------------------------------------------------------
// Elementwise tf32 rounding (prep)
// ---------------------------------------------------------------------------
__global__ __launch_bounds__(256) void cvt_rna_kernel(
    const float* __restrict__ in, float* __restrict__ out)
{
    int i = (blockIdx.x * 256 + threadIdx.x) * 4;
    float4 v = *(const float4*)(in + i);
    v.x = rna(v.x); v.y = rna(v.y); v.z = rna(v.z); v.w = rna(v.w);
    *(float4*)(out + i) = v;
}

// out[z][c][r] = rna(in[z][r][c]); in: R x C per z slice
__global__ __launch_bounds__(256) void transpose_cvt(
    const float* __restrict__ in, float* __restrict__ out,
    int R, int Ccols, long long zStride)
{
    __shared__ float t[32][33];
    const float* inz  = in  + blockIdx.z * zStride;
    float*       outz = out + blockIdx.z * zStride;
    const int r0 = blockIdx.y * 32;
    const int c0 = blockIdx.x * 32;
    const int tx = threadIdx.x & 31;
    const int ty = threadIdx.x >> 5;   // 0..7
#pragma unroll
    for (int k = 0; k < 4; k++)
        t[ty + k * 8][tx] = inz[(long long)(r0 + ty + k * 8) * Ccols + c0 + tx];
    __syncthreads();
#pragma unroll
    for (int k = 0; k < 4; k++)
        outz[(long long)(c0 + ty + k * 8) * R + r0 + tx] = rna(t[tx][ty + k * 8]);
}

// ---------------------------------------------------------------------------
// Row softmax over 2048 columns; float4 I/O; writes tf32-rounded probabilities
// ---------------------------------------------------------------------------
__global__ __launch_bounds__(256) void softmax2048(float* __restrict__ S)
{
    float4* row4 = (float4*)(S + (long long)blockIdx.x * SEQ);
    const int tid = threadIdx.x;

    float4 va = row4[tid];
    float4 vb = row4[tid + 256];
    float x[8] = {va.x, va.y, va.z, va.w, vb.x, vb.y, vb.z, vb.w};

    float m = x[0];
#pragma unroll
    for (int i = 1; i < 8; i++) m = fmaxf(m, x[i]);
#pragma unroll
    for (int o = 16; o > 0; o >>= 1)
        m = fmaxf(m, __shfl_xor_sync(0xffffffffu, m, o));

    __shared__ float red[8];
    if ((tid & 31) == 0) red[tid >> 5] = m;
    __syncthreads();
    float mAll = red[0];
#pragma unroll
    for (int i = 1; i < 8; i++) mAll = fmaxf(mAll, red[i]);
    __syncthreads();

    float s = 0.f;
#pragma unroll
    for (int i = 0; i < 8; i++) {
        x[i] = __expf(x[i] - mAll);
        s += x[i];
    }
#pragma unroll
    for (int o = 16; o > 0; o >>= 1)
        s += __shfl_xor_sync(0xffffffffu, s, o);
    if ((tid & 31) == 0) red[tid >> 5] = s;
    __syncthreads();
    float tot = 0.f;
#pragma unroll
    for (int i = 0; i < 8; i++) tot += red[i];

    const float inv = 1.f / tot;
#pragma unroll
    for (int i = 0; i < 8; i++) x[i] = rna(x[i] * inv);
    row4[tid]       = make_float4(x[0], x[1], x[2], x[3]);
    row4[tid + 256] = make_float4(x[4], x[5], x[6], x[7]);
}

// ---------------------------------------------------------------------------
// Launch
// ---------------------------------------------------------------------------
extern "C" void kernel_launch(void* const* d_in, const int* in_sizes, int n_in,
                              void* d_out, int out_size)
{
    const float* x = (const float*)d_in[0];   // [8, 2048, 768]
    const float* w = (const float*)d_in[1];   // [3, 768, 768]
    float* out     = (float*)d_out;           // [8, 2048, 768]

    float *xtf, *wt, *qkv, *sc;
    cudaGetSymbolAddress((void**)&xtf, g_xtf);
    cudaGetSymbolAddress((void**)&wt,  g_wt);
    cudaGetSymbolAddress((void**)&qkv, g_qkv);
    cudaGetSymbolAddress((void**)&sc,  g_s);

    const float INV_SCALE = 0.125f;  // 1 / sqrt(64)

    constexpr int SMEM_NN = (MBAR_FLOATS + STAGES * (ASZ + BDims<false>::SZ)) * 4;
    constexpr int SMEM_NT = (MBAR_FLOATS + STAGES * (ASZ + BDims<true>::SZ)) * 4;

    cudaFuncSetAttribute(mma_gemm<true, true>,
                         cudaFuncAttributeMaxDynamicSharedMemorySize, SMEM_NT);
    cudaFuncSetAttribute(mma_gemm<true, false>,
                         cudaFuncAttributeMaxDynamicSharedMemorySize, SMEM_NT);
    cudaFuncSetAttribute(mma_gemm<false, false>,
                         cudaFuncAttributeMaxDynamicSharedMemorySize, SMEM_NN);

    // 0) x -> tf32-rounded; W -> W^T tf32-rounded (QKV is NT for ldmatrix)
    cvt_rna_kernel<<<(BATCH * SEQ * DIM) / 1024, 256>>>(x, xtf);
    transpose_cvt<<<dim3(DIM / 32, DIM / 32, 3), 256>>>(
        w, wt, DIM, DIM, (long long)DIM * DIM);

    // 1) QKV (NT): qkv[z] = xtf @ wt[z]^T; outputs tf32-rounded
    {
        dim3 grid(DIM / BN, (BATCH * SEQ) / BM, 3);
        mma_gemm<true, true><<<grid, NTHREADS, SMEM_NT>>>(xtf, wt, qkv,
                                       BATCH * SEQ, DIM, DIM,
                                       0LL, (long long)DIM * DIM, BSD, 1.0f);
    }

    // 2) scores = Q @ K^T / 8  (NT, batched over 8)
    {
        dim3 grid(SEQ / BN, SEQ / BM, BATCH);
        mma_gemm<true, false><<<grid, NTHREADS, SMEM_NT>>>(qkv, qkv + BSD, sc,
                                      SEQ, SEQ, DIM,
                                      (long long)SEQ * DIM, (long long)SEQ * DIM,
                                      (long long)SEQ * SEQ, INV_SCALE);
    }

    // 3) softmax over last dim; writes tf32-rounded attn
    softmax2048<<<BATCH * SEQ, 256>>>(sc);

    // 4) out = attn @ V  (NN, batched over 8; ldmatrix on A only)
    {
        dim3 grid(DIM / BN, SEQ / BM, BATCH);
        mma_gemm<false, false><<<grid, NTHREADS, SMEM_NN>>>(sc, qkv + 2 * BSD, out,
                                       SEQ, DIM, SEQ,
                                       (long long)SEQ * SEQ, (long long)SEQ * DIM,
                                       (long long)SEQ * DIM, 1.0f);
    }
}

// round 13
// speedup vs baseline: 1.0831x; 1.0831x over previous
#include <cuda_runtime.h>
#include <cuda_bf16.h>
#include <cstdint>

// Problem constants
static constexpr int BATCH = 8;
static constexpr int SEQ   = 2048;
static constexpr int DIM   = 768;
static constexpr long long BSD = (long long)BATCH * SEQ * DIM;

// Scratch (device globals: allocation-free per harness rules). 16B-aligned for cp.async.
__device__ __align__(16) float g_xtf[BATCH * SEQ * DIM];      // x, tf32-rounded
__device__ __align__(16) float g_wt[3 * DIM * DIM];           // W^T per slice, tf32-rounded
__device__ __align__(16) float g_qkv[3 * BATCH * SEQ * DIM];  // q|k|v (tf32-rounded)
__device__ __align__(16) float g_vt[BATCH * DIM * SEQ];       // V^T per batch
__device__ __align__(16) float g_s[BATCH * SEQ * SEQ];        // scores / attn

__device__ __forceinline__ uint32_t f2tf32(float f) {
    uint32_t u;
    asm volatile("cvt.rna.tf32.f32 %0, %1;" : "=r"(u) : "f"(f));
    return u;
}
__device__ __forceinline__ float rna(float f) { return __uint_as_float(f2tf32(f)); }

__device__ __forceinline__ void mma_tf32(
    float& c0, float& c1, float& c2, float& c3,
    uint32_t a0, uint32_t a1, uint32_t a2, uint32_t a3,
    uint32_t b0, uint32_t b1)
{
    asm volatile(
        "mma.sync.aligned.m16n8k8.row.col.f32.tf32.tf32.f32 "
        "{%0,%1,%2,%3}, {%4,%5,%6,%7}, {%8,%9}, {%0,%1,%2,%3};\n"
        : "+f"(c0), "+f"(c1), "+f"(c2), "+f"(c3)
        : "r"(a0), "r"(a1), "r"(a2), "r"(a3), "r"(b0), "r"(b1));
}

__device__ __forceinline__ void ldmx4(uint32_t& r0, uint32_t& r1, uint32_t& r2, uint32_t& r3,
                                      uint32_t saddr)
{
    asm volatile("ldmatrix.sync.aligned.m8n8.x4.shared.b16 {%0,%1,%2,%3}, [%4];"
                 : "=r"(r0), "=r"(r1), "=r"(r2), "=r"(r3) : "r"(saddr));
}

__device__ __forceinline__ void cp16(void* smem_dst, const void* gsrc) {
    uint32_t sa = (uint32_t)__cvta_generic_to_shared(smem_dst);
    asm volatile("cp.async.cg.shared.global [%0], [%1], 16;\n" :: "r"(sa), "l"(gsrc));
}

// ---- mbarrier helpers ----
__device__ __forceinline__ void mbar_init(uint32_t a, uint32_t cnt) {
    asm volatile("mbarrier.init.shared.b64 [%0], %1;" :: "r"(a), "r"(cnt) : "memory");
}
__device__ __forceinline__ void mbar_arrive(uint32_t a) {
    asm volatile("mbarrier.arrive.shared.b64 _, [%0];" :: "r"(a) : "memory");
}
__device__ __forceinline__ void cpasync_mbar_arrive(uint32_t a) {
    asm volatile("cp.async.mbarrier.arrive.noinc.shared.b64 [%0];" :: "r"(a) : "memory");
}
__device__ __forceinline__ void mbar_wait(uint32_t a, uint32_t parity) {
    asm volatile(
        "{\n\t.reg .pred P;\n"
        "WL_%=:\n\t"
        "mbarrier.try_wait.parity.acquire.cta.shared::cta.b64 P, [%0], %1, 0x989680;\n\t"
        "@P bra.uni WD_%=;\n\t"
        "bra.uni WL_%=;\n"
        "WD_%=:\n\t}"
        :: "r"(a), "r"(parity) : "memory");
}

// ---------------------------------------------------------------------------
// tf32 tensor-core GEMM (NT only), 3-stage cp.async + per-stage mbarrier ring.
// C = alpha * A @ B^T; inputs already tf32-rounded.
//   A: [M,K] row-major; B: [N,K] row-major; C: [M,N]
// CTA 128x128x32, 8 warps (2x4), warp tile 64x32, ldmatrix both operands,
// mma m16n8k8; 2 CTAs/SM (R11/R12 evidence: this beats 512t single-CTA).
//   As [m][k] s36 ; Bs [n][k] s36
// full[s]: 256 cp.async arrivals; empty[s]: 8 per-warp arrivals; no
// __syncthreads in the main loop (warps drift; phases interleave).
// ---------------------------------------------------------------------------
#define BM 128
#define BN 128
#define BK 32
#define STAGES 3

static constexpr int TS_STRIDE = BK + 4;                 // 36
static constexpr int TSZ = BM * TS_STRIDE;               // floats per A or B stage
static constexpr int MBAR_FLOATS = 32;                   // 128 B for 3x(full,empty)
static constexpr int SMEM_GEMM = (MBAR_FLOATS + STAGES * 2 * TSZ) * 4;

template <bool ROUND>
__global__ __launch_bounds__(256, 2) void mma_gemm(
    const float* __restrict__ Ab, const float* __restrict__ Bb,
    float* __restrict__ Cb,
    int M, int N, int K,
    long long sA, long long sB, long long sC, float alpha)
{
    const float* A = Ab + (long long)blockIdx.z * sA;
    const float* B = Bb + (long long)blockIdx.z * sB;
    float*       C = Cb + (long long)blockIdx.z * sC;

    extern __shared__ float smem[];
    const uint32_t mb = (uint32_t)__cvta_generic_to_shared(smem);  // mbar area
    float* AsBase = smem + MBAR_FLOATS;
    float* BsBase = AsBase + STAGES * TSZ;

    const int tid  = threadIdx.x;
    const int warp = tid >> 5;
    const int lane = tid & 31;
    const int gid  = lane >> 2;   // 0..7
    const int tig  = lane & 3;    // 0..3
    const int wm   = (warp >> 2) * 64;
    const int wn   = (warp & 3) * 32;
    const int row0 = blockIdx.y * BM;
    const int col0 = blockIdx.x * BN;

    // mbarrier addresses: full[s] = mb + s*16, empty[s] = mb + s*16 + 8
    if (tid == 0) {
#pragma unroll
        for (int s = 0; s < STAGES; s++) {
            mbar_init(mb + s * 16, 256);    // full: one cp.async arrive per thread
            mbar_init(mb + s * 16 + 8, 8);  // empty: one arrive per warp
        }
    }
    __syncthreads();
    if (lane == 0) {
#pragma unroll
        for (int s = 0; s < STAGES; s++) mbar_arrive(mb + s * 16 + 8);
    }

    // ldmatrix per-lane byte offsets (verified R10/R11)
    const uint32_t laneAOff = (uint32_t)((lane & 15) * TS_STRIDE * 4 + (lane & 16));
    const uint32_t laneBOff = (uint32_t)(((lane & 7) + ((lane & 16) >> 1)) * TS_STRIDE * 4
                                         + (lane & 8) * 2);

    float c[4][4][4];
#pragma unroll
    for (int i = 0; i < 4; i++)
#pragma unroll
        for (int j = 0; j < 4; j++)
#pragma unroll
            for (int r = 0; r < 4; r++) c[i][j][r] = 0.f;

    const int aR = tid >> 3;            // 0..31 (+32/pass), 16B along k
    const int aC = (tid & 7) * 4;

    auto load_tile = [&](int stage, int kt) {
        float* As = AsBase + stage * TSZ;
        float* Bs = BsBase + stage * TSZ;
#pragma unroll
        for (int p = 0; p < 4; p++) {
            int r = aR + p * 32;
            cp16(&As[r * TS_STRIDE + aC], A + (long long)(row0 + r) * K + kt + aC);
        }
#pragma unroll
        for (int p = 0; p < 4; p++) {
            int r = aR + p * 32;
            cp16(&Bs[r * TS_STRIDE + aC], B + (long long)(col0 + r) * K + kt + aC);
        }
    };

    const int T = K / BK;

    // Producer cursor
    int ps = 0, pp = 0;
#pragma unroll
    for (int i = 0; i < STAGES; i++) {
        if (i < T) {
            mbar_wait(mb + ps * 16 + 8, pp);
            load_tile(ps, i * BK);
            cpasync_mbar_arrive(mb + ps * 16);
            if (++ps == STAGES) { ps = 0; pp ^= 1; }
        }
    }

    // Consumer cursor
    int cs = 0, cph = 0;
    for (int t = 0; t < T; t++) {
        mbar_wait(mb + cs * 16, cph);

        float* AsF = AsBase + cs * TSZ;
        float* BsF = BsBase + cs * TSZ;
        const uint32_t asAddr = (uint32_t)__cvta_generic_to_shared(AsF) + laneAOff;
        const uint32_t bsAddr = (uint32_t)__cvta_generic_to_shared(BsF) + laneBOff;

#pragma unroll
        for (int ks = 0; ks < BK; ks += 8) {
            uint32_t a[4][4];
#pragma unroll
            for (int i = 0; i < 4; i++)
                ldmx4(a[i][0], a[i][1], a[i][2], a[i][3],
                      asAddr + (uint32_t)(((wm + 16 * i) * TS_STRIDE + ks) * 4));
            uint32_t b[4][2];
#pragma unroll
            for (int jp = 0; jp < 2; jp++)
                ldmx4(b[2 * jp][0], b[2 * jp][1], b[2 * jp + 1][0], b[2 * jp + 1][1],
                      bsAddr + (uint32_t)(((wn + 16 * jp) * TS_STRIDE + ks) * 4));
#pragma unroll
            for (int i = 0; i < 4; i++)
#pragma unroll
                for (int j = 0; j < 4; j++)
                    mma_tf32(c[i][j][0], c[i][j][1], c[i][j][2], c[i][j][3],
                             a[i][0], a[i][1], a[i][2], a[i][3],
                             b[j][0], b[j][1]);
        }

        if (lane == 0) mbar_arrive(mb + cs * 16 + 8);
        if (++cs == STAGES) { cs = 0; cph ^= 1; }

        int nt = t + STAGES;
        if (nt < T) {
            mbar_wait(mb + ps * 16 + 8, pp);
            load_tile(ps, nt * BK);
            cpasync_mbar_arrive(mb + ps * 16);
            if (++ps == STAGES) { ps = 0; pp ^= 1; }
        }
    }

#pragma unroll
    for (int i = 0; i < 4; i++) {
        int rowA = row0 + wm + 16 * i + gid;
#pragma unroll
        for (int j = 0; j < 4; j++) {
            int col = col0 + wn + 8 * j + 2 * tig;
            float f0 = c[i][j][0] * alpha, f1 = c[i][j][1] * alpha;
            float f2 = c[i][j][2] * alpha, f3 = c[i][j][3] * alpha;
            if (ROUND) { f0 = rna(f0); f1 = rna(f1); f2 = rna(f2); f3 = rna(f3); }
            *(float2*)(C + (long long)rowA * N + col) = make_float2(f0, f1);
            *(float2*)(C + (long long)(rowA + 8) * N + col) = make_float2(f2, f3);
        }
    }
}

// ---------------------------------------------------------------------------
// Elementwise tf32 rounding (prep)
// ---------------------------------------------------------------------------
__global__ __launch_bounds__(256) void cvt_rna_kernel(
    const float* __restrict__ in, float* __restrict__ out)
{
    int i = (blockIdx.x * 256 + threadIdx.x) * 4;
    float4 v = *(const float4*)(in + i);
    v.x = rna(v.x); v.y = rna(v.y); v.z = rna(v.z); v.w = rna(v.w);
    *(float4*)(out + i) = v;
}

// out[z][c][r] = rna(in[z][r][c]); in: R x C per z slice (out stride = R)
__global__ __launch_bounds__(256) void transpose_cvt(
    const float* __restrict__ in, float* __restrict__ out,
    int R, int Ccols, long long zStride)
{
    __shared__ float t[32][33];
    const float* inz  = in  + blockIdx.z * zStride;
    float*       outz = out + blockIdx.z * zStride;
    const int r0 = blockIdx.y * 32;
    const int c0 = blockIdx.x * 32;
    const int tx = threadIdx.x & 31;
    const int ty = threadIdx.x >> 5;   // 0..7
#pragma unroll
    for (int k = 0; k < 4; k++)
        t[ty + k * 8][tx] = inz[(long long)(r0 + ty + k * 8) * Ccols + c0 + tx];
    __syncthreads();
#pragma unroll
    for (int k = 0; k < 4; k++)
        outz[(long long)(c0 + ty + k * 8) * R + r0 + tx] = rna(t[tx][ty + k * 8]);
}

// ---------------------------------------------------------------------------
// Row softmax over 2048 columns; float4 I/O; writes tf32-rounded probabilities
// ---------------------------------------------------------------------------
__global__ __launch_bounds__(256) void softmax2048(float* __restrict__ S)
{
    float4* row4 = (float4*)(S + (long long)blockIdx.x * SEQ);
    const int tid = threadIdx.x;

    float4 va = row4[tid];
    float4 vb = row4[tid + 256];
    float x[8] = {va.x, va.y, va.z, va.w, vb.x, vb.y, vb.z, vb.w};

    float m = x[0];
#pragma unroll
    for (int i = 1; i < 8; i++) m = fmaxf(m, x[i]);
#pragma unroll
    for (int o = 16; o > 0; o >>= 1)
        m = fmaxf(m, __shfl_xor_sync(0xffffffffu, m, o));

    __shared__ float red[8];
    if ((tid & 31) == 0) red[tid >> 5] = m;
    __syncthreads();
    float mAll = red[0];
#pragma unroll
    for (int i = 1; i < 8; i++) mAll = fmaxf(mAll, red[i]);
    __syncthreads();

    float s = 0.f;
#pragma unroll
    for (int i = 0; i < 8; i++) {
        x[i] = __expf(x[i] - mAll);
        s += x[i];
    }
#pragma unroll
    for (int o = 16; o > 0; o >>= 1)
        s += __shfl_xor_sync(0xffffffffu, s, o);
    if ((tid & 31) == 0) red[tid >> 5] = s;
    __syncthreads();
    float tot = 0.f;
#pragma unroll
    for (int i = 0; i < 8; i++) tot += red[i];

    const float inv = 1.f / tot;
#pragma unroll
    for (int i = 0; i < 8; i++) x[i] = rna(x[i] * inv);
    row4[tid]       = make_float4(x[0], x[1], x[2], x[3]);
    row4[tid + 256] = make_float4(x[4], x[5], x[6], x[7]);
}

// ---------------------------------------------------------------------------
// Launch
// ---------------------------------------------------------------------------
extern "C" void kernel_launch(void* const* d_in, const int* in_sizes, int n_in,
                              void* d_out, int out_size)
{
    const float* x = (const float*)d_in[0];   // [8, 2048, 768]
    const float* w = (const float*)d_in[1];   // [3, 768, 768]
    float* out     = (float*)d_out;           // [8, 2048, 768]

    float *xtf, *wt, *qkv, *vt, *sc;
    cudaGetSymbolAddress((void**)&xtf, g_xtf);
    cudaGetSymbolAddress((void**)&wt,  g_wt);
    cudaGetSymbolAddress((void**)&qkv, g_qkv);
    cudaGetSymbolAddress((void**)&vt,  g_vt);
    cudaGetSymbolAddress((void**)&sc,  g_s);

    const float INV_SCALE = 0.125f;  // 1 / sqrt(64)

    cudaFuncSetAttribute(mma_gemm<true>,
                         cudaFuncAttributeMaxDynamicSharedMemorySize, SMEM_GEMM);
    cudaFuncSetAttribute(mma_gemm<false>,
                         cudaFuncAttributeMaxDynamicSharedMemorySize, SMEM_GEMM);

    // 0) x -> tf32-rounded; W -> W^T tf32-rounded (all GEMMs are NT)
    cvt_rna_kernel<<<(BATCH * SEQ * DIM) / 1024, 256>>>(x, xtf);
    transpose_cvt<<<dim3(DIM / 32, DIM / 32, 3), 256>>>(
        w, wt, DIM, DIM, (long long)DIM * DIM);

    // 1) QKV (NT): qkv[z] = xtf @ wt[z]^T; outputs tf32-rounded
    {
        dim3 grid(DIM / BN, (BATCH * SEQ) / BM, 3);
        mma_gemm<true><<<grid, 256, SMEM_GEMM>>>(xtf, wt, qkv,
                                       BATCH * SEQ, DIM, DIM,
                                       0LL, (long long)DIM * DIM, BSD, 1.0f);
    }

    // 1b) V -> V^T per batch (rna idempotent on already-rounded values)
    transpose_cvt<<<dim3(DIM / 32, SEQ / 32, BATCH), 256>>>(
        qkv + 2 * BSD, vt, SEQ, DIM, (long long)SEQ * DIM);

    // 2) scores = Q @ K^T / 8  (NT, batched over 8)
    {
        dim3 grid(SEQ / BN, SEQ / BM, BATCH);
        mma_gemm<false><<<grid, 256, SMEM_GEMM>>>(qkv, qkv + BSD, sc,
                                      SEQ, SEQ, DIM,
                                      (long long)SEQ * DIM, (long long)SEQ * DIM,
                                      (long long)SEQ * SEQ, INV_SCALE);
    }

    // 3) softmax over last dim; writes tf32-rounded attn
    softmax2048<<<BATCH * SEQ, 256>>>(sc);

    // 4) out = attn @ (V^T)^T  (NT, batched over 8; ldmatrix both operands)
    {
        dim3 grid(DIM / BN, SEQ / BM, BATCH);
        mma_gemm<false><<<grid, 256, SMEM_GEMM>>>(sc, vt, out,
                                       SEQ, DIM, SEQ,
                                       (long long)SEQ * SEQ, (long long)DIM * SEQ,
                                       (long long)SEQ * DIM, 1.0f);
    }
}

// round 14
// speedup vs baseline: 1.1091x; 1.0239x over previous
#include <cuda_runtime.h>
#include <cuda_bf16.h>
#include <cstdint>

// Problem constants
static constexpr int BATCH = 8;
static constexpr int SEQ   = 2048;
static constexpr int DIM   = 768;
static constexpr long long BSD = (long long)BATCH * SEQ * DIM;

// Scratch (device globals: allocation-free per harness rules). 16B-aligned for cp.async.
__device__ __align__(16) float g_xtf[BATCH * SEQ * DIM];      // x, tf32-rounded
__device__ __align__(16) float g_wt[3 * DIM * DIM];           // W^T per slice, tf32-rounded
__device__ __align__(16) float g_qkv[3 * BATCH * SEQ * DIM];  // q|k|v (tf32-rounded)
__device__ __align__(16) float g_vt[BATCH * DIM * SEQ];       // V^T per batch
__device__ __align__(16) float g_s[BATCH * SEQ * SEQ];        // scores / attn

__device__ __forceinline__ uint32_t f2tf32(float f) {
    uint32_t u;
    asm volatile("cvt.rna.tf32.f32 %0, %1;" : "=r"(u) : "f"(f));
    return u;
}
__device__ __forceinline__ float rna(float f) { return __uint_as_float(f2tf32(f)); }

__device__ __forceinline__ void mma_tf32(
    float& c0, float& c1, float& c2, float& c3,
    uint32_t a0, uint32_t a1, uint32_t a2, uint32_t a3,
    uint32_t b0, uint32_t b1)
{
    asm volatile(
        "mma.sync.aligned.m16n8k8.row.col.f32.tf32.tf32.f32 "
        "{%0,%1,%2,%3}, {%4,%5,%6,%7}, {%8,%9}, {%0,%1,%2,%3};\n"
        : "+f"(c0), "+f"(c1), "+f"(c2), "+f"(c3)
        : "r"(a0), "r"(a1), "r"(a2), "r"(a3), "r"(b0), "r"(b1));
}

__device__ __forceinline__ void ldmx4(uint32_t& r0, uint32_t& r1, uint32_t& r2, uint32_t& r3,
                                      uint32_t saddr)
{
    asm volatile("ldmatrix.sync.aligned.m8n8.x4.shared.b16 {%0,%1,%2,%3}, [%4];"
                 : "=r"(r0), "=r"(r1), "=r"(r2), "=r"(r3) : "r"(saddr));
}

__device__ __forceinline__ void cp16(void* smem_dst, const void* gsrc) {
    uint32_t sa = (uint32_t)__cvta_generic_to_shared(smem_dst);
    asm volatile("cp.async.cg.shared.global [%0], [%1], 16;\n" :: "r"(sa), "l"(gsrc));
}

// ---- mbarrier helpers ----
__device__ __forceinline__ void mbar_init(uint32_t a, uint32_t cnt) {
    asm volatile("mbarrier.init.shared.b64 [%0], %1;" :: "r"(a), "r"(cnt) : "memory");
}
__device__ __forceinline__ void mbar_arrive(uint32_t a) {
    asm volatile("mbarrier.arrive.shared.b64 _, [%0];" :: "r"(a) : "memory");
}
__device__ __forceinline__ void cpasync_mbar_arrive(uint32_t a) {
    asm volatile("cp.async.mbarrier.arrive.noinc.shared.b64 [%0];" :: "r"(a) : "memory");
}
__device__ __forceinline__ void mbar_wait(uint32_t a, uint32_t parity) {
    asm volatile(
        "{\n\t.reg .pred P;\n"
        "WL_%=:\n\t"
        "mbarrier.try_wait.parity.acquire.cta.shared::cta.b64 P, [%0], %1, 0x989680;\n\t"
        "@P bra.uni WD_%=;\n\t"
        "bra.uni WL_%=;\n"
        "WD_%=:\n\t}"
        :: "r"(a), "r"(parity) : "memory");
}

// ---------------------------------------------------------------------------
// tf32 tensor-core GEMM (NT only), 3-stage cp.async + per-stage mbarrier ring.
// C = alpha * A @ B^T; inputs already tf32-rounded.
//   A: [M,K] row-major; B: [N,K] row-major; C: [M,N]
// R14: CTA 128x128x32 with FOUR warps (128 threads), warp tile 64x64 (2x2).
// A and B are each reread by only 2 warps (vs 4/2 at 64x32) -> smem traffic
// per CTA k-tile drops 128KB -> 96KB; LDS-per-MMA 0.375 -> 0.25.
// 2 CTAs/SM; mbarrier ring (no block barrier in loop) keeps CTAs decohered.
//   As [m][k] s36 ; Bs [n][k] s36
// full[s]: 128 cp.async arrivals; empty[s]: 4 per-warp arrivals.
// ---------------------------------------------------------------------------
#define BM 128
#define BN 128
#define BK 32
#define NTHREADS 128
#define NWARPS 4
#define STAGES 3

static constexpr int TS_STRIDE = BK + 4;                 // 36
static constexpr int TSZ = BM * TS_STRIDE;               // floats per A or B stage
static constexpr int MBAR_FLOATS = 32;                   // 128 B for 3x(full,empty)
static constexpr int SMEM_GEMM = (MBAR_FLOATS + STAGES * 2 * TSZ) * 4;

template <bool ROUND>
__global__ __launch_bounds__(NTHREADS, 2) void mma_gemm(
    const float* __restrict__ Ab, const float* __restrict__ Bb,
    float* __restrict__ Cb,
    int M, int N, int K,
    long long sA, long long sB, long long sC, float alpha)
{
    const float* A = Ab + (long long)blockIdx.z * sA;
    const float* B = Bb + (long long)blockIdx.z * sB;
    float*       C = Cb + (long long)blockIdx.z * sC;

    extern __shared__ float smem[];
    const uint32_t mb = (uint32_t)__cvta_generic_to_shared(smem);  // mbar area
    float* AsBase = smem + MBAR_FLOATS;
    float* BsBase = AsBase + STAGES * TSZ;

    const int tid  = threadIdx.x;
    const int warp = tid >> 5;        // 0..3
    const int lane = tid & 31;
    const int gid  = lane >> 2;       // 0..7
    const int tig  = lane & 3;        // 0..3
    const int wm   = (warp >> 1) * 64;  // 0 or 64
    const int wn   = (warp & 1) * 64;   // 0 or 64
    const int row0 = blockIdx.y * BM;
    const int col0 = blockIdx.x * BN;

    // mbarrier addresses: full[s] = mb + s*16, empty[s] = mb + s*16 + 8
    if (tid == 0) {
#pragma unroll
        for (int s = 0; s < STAGES; s++) {
            mbar_init(mb + s * 16, NTHREADS);   // full: one cp.async arrive per thread
            mbar_init(mb + s * 16 + 8, NWARPS); // empty: one arrive per warp
        }
    }
    __syncthreads();
    if (lane == 0) {
#pragma unroll
        for (int s = 0; s < STAGES; s++) mbar_arrive(mb + s * 16 + 8);
    }

    // ldmatrix per-lane byte offsets (verified R10-R13)
    const uint32_t laneAOff = (uint32_t)((lane & 15) * TS_STRIDE * 4 + (lane & 16));
    const uint32_t laneBOff = (uint32_t)(((lane & 7) + ((lane & 16) >> 1)) * TS_STRIDE * 4
                                         + (lane & 8) * 2);

    // Accumulators: 4 m-frags x 8 n-frags x 4 regs = 128 regs
    float c[4][8][4];
#pragma unroll
    for (int i = 0; i < 4; i++)
#pragma unroll
        for (int j = 0; j < 8; j++)
#pragma unroll
            for (int r = 0; r < 4; r++) c[i][j][r] = 0.f;

    // Loader indices (128 threads): 16 rows x 8 cp16 per pass, 8 passes/tile
    const int aR = tid >> 3;            // 0..15 (+16/pass), 16B along k
    const int aC = (tid & 7) * 4;

    auto load_tile = [&](int stage, int kt) {
        float* As = AsBase + stage * TSZ;
        float* Bs = BsBase + stage * TSZ;
#pragma unroll
        for (int p = 0; p < 8; p++) {
            int r = aR + p * 16;
            cp16(&As[r * TS_STRIDE + aC], A + (long long)(row0 + r) * K + kt + aC);
        }
#pragma unroll
        for (int p = 0; p < 8; p++) {
            int r = aR + p * 16;
            cp16(&Bs[r * TS_STRIDE + aC], B + (long long)(col0 + r) * K + kt + aC);
        }
    };

    const int T = K / BK;

    // Producer cursor
    int ps = 0, pp = 0;
#pragma unroll
    for (int i = 0; i < STAGES; i++) {
        if (i < T) {
            mbar_wait(mb + ps * 16 + 8, pp);
            load_tile(ps, i * BK);
            cpasync_mbar_arrive(mb + ps * 16);
            if (++ps == STAGES) { ps = 0; pp ^= 1; }
        }
    }

    // Consumer cursor
    int cs = 0, cph = 0;
    for (int t = 0; t < T; t++) {
        mbar_wait(mb + cs * 16, cph);

        float* AsF = AsBase + cs * TSZ;
        float* BsF = BsBase + cs * TSZ;
        const uint32_t asAddr = (uint32_t)__cvta_generic_to_shared(AsF) + laneAOff;
        const uint32_t bsAddr = (uint32_t)__cvta_generic_to_shared(BsF) + laneBOff;

#pragma unroll
        for (int ks = 0; ks < BK; ks += 8) {
            uint32_t a[4][4];
#pragma unroll
            for (int i = 0; i < 4; i++)
                ldmx4(a[i][0], a[i][1], a[i][2], a[i][3],
                      asAddr + (uint32_t)(((wm + 16 * i) * TS_STRIDE + ks) * 4));
            uint32_t b[8][2];
#pragma unroll
            for (int jp = 0; jp < 4; jp++)
                ldmx4(b[2 * jp][0], b[2 * jp][1], b[2 * jp + 1][0], b[2 * jp + 1][1],
                      bsAddr + (uint32_t)(((wn + 16 * jp) * TS_STRIDE + ks) * 4));
#pragma unroll
            for (int i = 0; i < 4; i++)
#pragma unroll
                for (int j = 0; j < 8; j++)
                    mma_tf32(c[i][j][0], c[i][j][1], c[i][j][2], c[i][j][3],
                             a[i][0], a[i][1], a[i][2], a[i][3],
                             b[j][0], b[j][1]);
        }

        if (lane == 0) mbar_arrive(mb + cs * 16 + 8);
        if (++cs == STAGES) { cs = 0; cph ^= 1; }

        int nt = t + STAGES;
        if (nt < T) {
            mbar_wait(mb + ps * 16 + 8, pp);
            load_tile(ps, nt * BK);
            cpasync_mbar_arrive(mb + ps * 16);
            if (++ps == STAGES) { ps = 0; pp ^= 1; }
        }
    }

#pragma unroll
    for (int i = 0; i < 4; i++) {
        int rowA = row0 + wm + 16 * i + gid;
#pragma unroll
        for (int j = 0; j < 8; j++) {
            int col = col0 + wn + 8 * j + 2 * tig;
            float f0 = c[i][j][0] * alpha, f1 = c[i][j][1] * alpha;
            float f2 = c[i][j][2] * alpha, f3 = c[i][j][3] * alpha;
            if (ROUND) { f0 = rna(f0); f1 = rna(f1); f2 = rna(f2); f3 = rna(f3); }
            *(float2*)(C + (long long)rowA * N + col) = make_float2(f0, f1);
            *(float2*)(C + (long long)(rowA + 8) * N + col) = make_float2(f2, f3);
        }
    }
}

// ---------------------------------------------------------------------------
// Elementwise tf32 rounding (prep)
// ---------------------------------------------------------------------------
__global__ __launch_bounds__(256) void cvt_rna_kernel(
    const float* __restrict__ in, float* __restrict__ out)
{
    int i = (blockIdx.x * 256 + threadIdx.x) * 4;
    float4 v = *(const float4*)(in + i);
    v.x = rna(v.x); v.y = rna(v.y); v.z = rna(v.z); v.w = rna(v.w);
    *(float4*)(out + i) = v;
}

// out[z][c][r] = rna(in[z][r][c]); in: R x C per z slice (out stride = R)
__global__ __launch_bounds__(256) void transpose_cvt(
    const float* __restrict__ in, float* __restrict__ out,
    int R, int Ccols, long long zStride)
{
    __shared__ float t[32][33];
    const float* inz  = in  + blockIdx.z * zStride;
    float*       outz = out + blockIdx.z * zStride;
    const int r0 = blockIdx.y * 32;
    const int c0 = blockIdx.x * 32;
    const int tx = threadIdx.x & 31;
    const int ty = threadIdx.x >> 5;   // 0..7
#pragma unroll
    for (int k = 0; k < 4; k++)
        t[ty + k * 8][tx] = inz[(long long)(r0 + ty + k * 8) * Ccols + c0 + tx];
    __syncthreads();
#pragma unroll
    for (int k = 0; k < 4; k++)
        outz[(long long)(c0 + ty + k * 8) * R + r0 + tx] = rna(t[tx][ty + k * 8]);
}

// ---------------------------------------------------------------------------
// Row softmax over 2048 columns; float4 I/O; writes tf32-rounded probabilities
// ---------------------------------------------------------------------------
__global__ __launch_bounds__(256) void softmax2048(float* __restrict__ S)
{
    float4* row4 = (float4*)(S + (long long)blockIdx.x * SEQ);
    const int tid = threadIdx.x;

    float4 va = row4[tid];
    float4 vb = row4[tid + 256];
    float x[8] = {va.x, va.y, va.z, va.w, vb.x, vb.y, vb.z, vb.w};

    float m = x[0];
#pragma unroll
    for (int i = 1; i < 8; i++) m = fmaxf(m, x[i]);
#pragma unroll
    for (int o = 16; o > 0; o >>= 1)
        m = fmaxf(m, __shfl_xor_sync(0xffffffffu, m, o));

    __shared__ float red[8];
    if ((tid & 31) == 0) red[tid >> 5] = m;
    __syncthreads();
    float mAll = red[0];
#pragma unroll
    for (int i = 1; i < 8; i++) mAll = fmaxf(mAll, red[i]);
    __syncthreads();

    float s = 0.f;
#pragma unroll
    for (int i = 0; i < 8; i++) {
        x[i] = __expf(x[i] - mAll);
        s += x[i];
    }
#pragma unroll
    for (int o = 16; o > 0; o >>= 1)
        s += __shfl_xor_sync(0xffffffffu, s, o);
    if ((tid & 31) == 0) red[tid >> 5] = s;
    __syncthreads();
    float tot = 0.f;
#pragma unroll
    for (int i = 0; i < 8; i++) tot += red[i];

    const float inv = 1.f / tot;
#pragma unroll
    for (int i = 0; i < 8; i++) x[i] = rna(x[i] * inv);
    row4[tid]       = make_float4(x[0], x[1], x[2], x[3]);
    row4[tid + 256] = make_float4(x[4], x[5], x[6], x[7]);
}

// ---------------------------------------------------------------------------
// Launch
// ---------------------------------------------------------------------------
extern "C" void kernel_launch(void* const* d_in, const int* in_sizes, int n_in,
                              void* d_out, int out_size)
{
    const float* x = (const float*)d_in[0];   // [8, 2048, 768]
    const float* w = (const float*)d_in[1];   // [3, 768, 768]
    float* out     = (float*)d_out;           // [8, 2048, 768]

    float *xtf, *wt, *qkv, *vt, *sc;
    cudaGetSymbolAddress((void**)&xtf, g_xtf);
    cudaGetSymbolAddress((void**)&wt,  g_wt);
    cudaGetSymbolAddress((void**)&qkv, g_qkv);
    cudaGetSymbolAddress((void**)&vt,  g_vt);
    cudaGetSymbolAddress((void**)&sc,  g_s);

    const float INV_SCALE = 0.125f;  // 1 / sqrt(64)

    cudaFuncSetAttribute(mma_gemm<true>,
                         cudaFuncAttributeMaxDynamicSharedMemorySize, SMEM_GEMM);
    cudaFuncSetAttribute(mma_gemm<false>,
                         cudaFuncAttributeMaxDynamicSharedMemorySize, SMEM_GEMM);

    // 0) x -> tf32-rounded; W -> W^T tf32-rounded (all GEMMs are NT)
    cvt_rna_kernel<<<(BATCH * SEQ * DIM) / 1024, 256>>>(x, xtf);
    transpose_cvt<<<dim3(DIM / 32, DIM / 32, 3), 256>>>(
        w, wt, DIM, DIM, (long long)DIM * DIM);

    // 1) QKV (NT): qkv[z] = xtf @ wt[z]^T; outputs tf32-rounded
    {
        dim3 grid(DIM / BN, (BATCH * SEQ) / BM, 3);
        mma_gemm<true><<<grid, NTHREADS, SMEM_GEMM>>>(xtf, wt, qkv,
                                       BATCH * SEQ, DIM, DIM,
                                       0LL, (long long)DIM * DIM, BSD, 1.0f);
    }

    // 1b) V -> V^T per batch (rna idempotent on already-rounded values)
    transpose_cvt<<<dim3(DIM / 32, SEQ / 32, BATCH), 256>>>(
        qkv + 2 * BSD, vt, SEQ, DIM, (long long)SEQ * DIM);

    // 2) scores = Q @ K^T / 8  (NT, batched over 8)
    {
        dim3 grid(SEQ / BN, SEQ / BM, BATCH);
        mma_gemm<false><<<grid, NTHREADS, SMEM_GEMM>>>(qkv, qkv + BSD, sc,
                                      SEQ, SEQ, DIM,
                                      (long long)SEQ * DIM, (long long)SEQ * DIM,
                                      (long long)SEQ * SEQ, INV_SCALE);
    }

    // 3) softmax over last dim; writes tf32-rounded attn
    softmax2048<<<BATCH * SEQ, 256>>>(sc);

    // 4) out = attn @ (V^T)^T  (NT, batched over 8; ldmatrix both operands)
    {
        dim3 grid(DIM / BN, SEQ / BM, BATCH);
        mma_gemm<false><<<grid, NTHREADS, SMEM_GEMM>>>(sc, vt, out,
                                       SEQ, DIM, SEQ,
                                       (long long)SEQ * SEQ, (long long)DIM * SEQ,
                                       (long long)SEQ * DIM, 1.0f);
    }
}

// round 15
// speedup vs baseline: 1.1101x; 1.0009x over previous
#include <cuda_runtime.h>
#include <cuda_bf16.h>
#include <cstdint>

// Problem constants
static constexpr int BATCH = 8;
static constexpr int SEQ   = 2048;
static constexpr int DIM   = 768;
static constexpr long long BSD = (long long)BATCH * SEQ * DIM;

// Scratch (device globals: allocation-free per harness rules). 16B-aligned for cp.async.
__device__ __align__(16) float g_xtf[BATCH * SEQ * DIM];      // x, tf32-rounded
__device__ __align__(16) float g_wt[3 * DIM * DIM];           // W^T per slice, tf32-rounded
__device__ __align__(16) float g_qkv[3 * BATCH * SEQ * DIM];  // q|k|v (tf32-rounded)
__device__ __align__(16) float g_vt[BATCH * DIM * SEQ];       // V^T per batch
__device__ __align__(16) float g_s[BATCH * SEQ * SEQ];        // scores / attn

__device__ __forceinline__ uint32_t f2tf32(float f) {
    uint32_t u;
    asm volatile("cvt.rna.tf32.f32 %0, %1;" : "=r"(u) : "f"(f));
    return u;
}
__device__ __forceinline__ float rna(float f) { return __uint_as_float(f2tf32(f)); }

__device__ __forceinline__ void mma_tf32(
    float& c0, float& c1, float& c2, float& c3,
    uint32_t a0, uint32_t a1, uint32_t a2, uint32_t a3,
    uint32_t b0, uint32_t b1)
{
    asm volatile(
        "mma.sync.aligned.m16n8k8.row.col.f32.tf32.tf32.f32 "
        "{%0,%1,%2,%3}, {%4,%5,%6,%7}, {%8,%9}, {%0,%1,%2,%3};\n"
        : "+f"(c0), "+f"(c1), "+f"(c2), "+f"(c3)
        : "r"(a0), "r"(a1), "r"(a2), "r"(a3), "r"(b0), "r"(b1));
}

__device__ __forceinline__ void ldmx4(uint32_t& r0, uint32_t& r1, uint32_t& r2, uint32_t& r3,
                                      uint32_t saddr)
{
    asm volatile("ldmatrix.sync.aligned.m8n8.x4.shared.b16 {%0,%1,%2,%3}, [%4];"
                 : "=r"(r0), "=r"(r1), "=r"(r2), "=r"(r3) : "r"(saddr));
}

__device__ __forceinline__ void cp16(void* smem_dst, const void* gsrc) {
    uint32_t sa = (uint32_t)__cvta_generic_to_shared(smem_dst);
    asm volatile("cp.async.cg.shared.global [%0], [%1], 16;\n" :: "r"(sa), "l"(gsrc));
}

// ---- mbarrier helpers ----
__device__ __forceinline__ void mbar_init(uint32_t a, uint32_t cnt) {
    asm volatile("mbarrier.init.shared.b64 [%0], %1;" :: "r"(a), "r"(cnt) : "memory");
}
__device__ __forceinline__ void mbar_arrive(uint32_t a) {
    asm volatile("mbarrier.arrive.shared.b64 _, [%0];" :: "r"(a) : "memory");
}
__device__ __forceinline__ void cpasync_mbar_arrive(uint32_t a) {
    asm volatile("cp.async.mbarrier.arrive.noinc.shared.b64 [%0];" :: "r"(a) : "memory");
}
__device__ __forceinline__ void mbar_wait(uint32_t a, uint32_t parity) {
    asm volatile(
        "{\n\t.reg .pred P;\n"
        "WL_%=:\n\t"
        "mbarrier.try_wait.parity.acquire.cta.shared::cta.b64 P, [%0], %1, 0x989680;\n\t"
        "@P bra.uni WD_%=;\n\t"
        "bra.uni WL_%=;\n"
        "WD_%=:\n\t}"
        :: "r"(a), "r"(parity) : "memory");
}

// ---------------------------------------------------------------------------
// tf32 tensor-core GEMM (NT only), 3-stage cp.async + per-stage mbarrier ring.
// C = alpha * A @ B^T; inputs already tf32-rounded.
//   A: [M,K] row-major; B: [N,K] row-major; C: [M,N]
// CTA 128x128x32, 4 warps (128 threads), warp tile 64x64; 2 CTAs/SM.
// R15: (1) fragment double-buffering — ldmatrix for k-step ks+1 issues under
// the 32 MMAs of k-step ks, hiding LDS latency inside the warp;
// (2) early empty-arrive — the stage's last smem read is the final ldmatrix,
// so arrive(empty) fires there (release orders prior reads), freeing the
// stage for the producer one full MMA-chain earlier.
//   As [m][k] s36 ; Bs [n][k] s36
// full[s]: 128 cp.async arrivals; empty[s]: 4 per-warp arrivals.
// ---------------------------------------------------------------------------
#define BM 128
#define BN 128
#define BK 32
#define NTHREADS 128
#define NWARPS 4
#define STAGES 3

static constexpr int TS_STRIDE = BK + 4;                 // 36
static constexpr int TSZ = BM * TS_STRIDE;               // floats per A or B stage
static constexpr int MBAR_FLOATS = 32;                   // 128 B for 3x(full,empty)
static constexpr int SMEM_GEMM = (MBAR_FLOATS + STAGES * 2 * TSZ) * 4;

template <bool ROUND>
__global__ __launch_bounds__(NTHREADS, 2) void mma_gemm(
    const float* __restrict__ Ab, const float* __restrict__ Bb,
    float* __restrict__ Cb,
    int M, int N, int K,
    long long sA, long long sB, long long sC, float alpha)
{
    const float* A = Ab + (long long)blockIdx.z * sA;
    const float* B = Bb + (long long)blockIdx.z * sB;
    float*       C = Cb + (long long)blockIdx.z * sC;

    extern __shared__ float smem[];
    const uint32_t mb = (uint32_t)__cvta_generic_to_shared(smem);  // mbar area
    float* AsBase = smem + MBAR_FLOATS;
    float* BsBase = AsBase + STAGES * TSZ;

    const int tid  = threadIdx.x;
    const int warp = tid >> 5;        // 0..3
    const int lane = tid & 31;
    const int gid  = lane >> 2;       // 0..7
    const int tig  = lane & 3;        // 0..3
    const int wm   = (warp >> 1) * 64;  // 0 or 64
    const int wn   = (warp & 1) * 64;   // 0 or 64
    const int row0 = blockIdx.y * BM;
    const int col0 = blockIdx.x * BN;

    if (tid == 0) {
#pragma unroll
        for (int s = 0; s < STAGES; s++) {
            mbar_init(mb + s * 16, NTHREADS);   // full: one cp.async arrive per thread
            mbar_init(mb + s * 16 + 8, NWARPS); // empty: one arrive per warp
        }
    }
    __syncthreads();
    if (lane == 0) {
#pragma unroll
        for (int s = 0; s < STAGES; s++) mbar_arrive(mb + s * 16 + 8);
    }

    // ldmatrix per-lane byte offsets (verified R10-R14)
    const uint32_t laneAOff = (uint32_t)((lane & 15) * TS_STRIDE * 4 + (lane & 16));
    const uint32_t laneBOff = (uint32_t)(((lane & 7) + ((lane & 16) >> 1)) * TS_STRIDE * 4
                                         + (lane & 8) * 2);

    // Accumulators: 4 m-frags x 8 n-frags x 4 regs = 128 regs
    float c[4][8][4];
#pragma unroll
    for (int i = 0; i < 4; i++)
#pragma unroll
        for (int j = 0; j < 8; j++)
#pragma unroll
            for (int r = 0; r < 4; r++) c[i][j][r] = 0.f;

    const int aR = tid >> 3;            // 0..15 (+16/pass), 16B along k
    const int aC = (tid & 7) * 4;

    auto load_tile = [&](int stage, int kt) {
        float* As = AsBase + stage * TSZ;
        float* Bs = BsBase + stage * TSZ;
#pragma unroll
        for (int p = 0; p < 8; p++) {
            int r = aR + p * 16;
            cp16(&As[r * TS_STRIDE + aC], A + (long long)(row0 + r) * K + kt + aC);
        }
#pragma unroll
        for (int p = 0; p < 8; p++) {
            int r = aR + p * 16;
            cp16(&Bs[r * TS_STRIDE + aC], B + (long long)(col0 + r) * K + kt + aC);
        }
    };

    const int T = K / BK;

    // Producer cursor
    int ps = 0, pp = 0;
#pragma unroll
    for (int i = 0; i < STAGES; i++) {
        if (i < T) {
            mbar_wait(mb + ps * 16 + 8, pp);
            load_tile(ps, i * BK);
            cpasync_mbar_arrive(mb + ps * 16);
            if (++ps == STAGES) { ps = 0; pp ^= 1; }
        }
    }

    // Consumer cursor
    int cs = 0, cph = 0;
    for (int t = 0; t < T; t++) {
        mbar_wait(mb + cs * 16, cph);

        float* AsF = AsBase + cs * TSZ;
        float* BsF = BsBase + cs * TSZ;
        const uint32_t asAddr = (uint32_t)__cvta_generic_to_shared(AsF) + laneAOff;
        const uint32_t bsAddr = (uint32_t)__cvta_generic_to_shared(BsF) + laneBOff;

        // Double-buffered fragments: load ks+1 under the MMAs of ks.
        uint32_t a[2][4][4];
        uint32_t b[2][8][2];

        // Load k-step 0 fragments.
#pragma unroll
        for (int i = 0; i < 4; i++)
            ldmx4(a[0][i][0], a[0][i][1], a[0][i][2], a[0][i][3],
                  asAddr + (uint32_t)(((wm + 16 * i) * TS_STRIDE) * 4));
#pragma unroll
        for (int jp = 0; jp < 4; jp++)
            ldmx4(b[0][2 * jp][0], b[0][2 * jp][1], b[0][2 * jp + 1][0], b[0][2 * jp + 1][1],
                  bsAddr + (uint32_t)(((wn + 16 * jp) * TS_STRIDE) * 4));

#pragma unroll
        for (int kk = 0; kk < BK / 8; kk++) {
            const int cur = kk & 1;
            if (kk < BK / 8 - 1) {
                const int nxt = cur ^ 1;
                const int ks = (kk + 1) * 8;
#pragma unroll
                for (int i = 0; i < 4; i++)
                    ldmx4(a[nxt][i][0], a[nxt][i][1], a[nxt][i][2], a[nxt][i][3],
                          asAddr + (uint32_t)(((wm + 16 * i) * TS_STRIDE + ks) * 4));
#pragma unroll
                for (int jp = 0; jp < 4; jp++)
                    ldmx4(b[nxt][2 * jp][0], b[nxt][2 * jp][1],
                          b[nxt][2 * jp + 1][0], b[nxt][2 * jp + 1][1],
                          bsAddr + (uint32_t)(((wn + 16 * jp) * TS_STRIDE + ks) * 4));
            } else {
                // Last smem read of this stage already issued: free the stage now.
                if (lane == 0) mbar_arrive(mb + cs * 16 + 8);
            }
#pragma unroll
            for (int i = 0; i < 4; i++)
#pragma unroll
                for (int j = 0; j < 8; j++)
                    mma_tf32(c[i][j][0], c[i][j][1], c[i][j][2], c[i][j][3],
                             a[cur][i][0], a[cur][i][1], a[cur][i][2], a[cur][i][3],
                             b[cur][j][0], b[cur][j][1]);
        }

        if (++cs == STAGES) { cs = 0; cph ^= 1; }

        int nt = t + STAGES;
        if (nt < T) {
            mbar_wait(mb + ps * 16 + 8, pp);
            load_tile(ps, nt * BK);
            cpasync_mbar_arrive(mb + ps * 16);
            if (++ps == STAGES) { ps = 0; pp ^= 1; }
        }
    }

#pragma unroll
    for (int i = 0; i < 4; i++) {
        int rowA = row0 + wm + 16 * i + gid;
#pragma unroll
        for (int j = 0; j < 8; j++) {
            int col = col0 + wn + 8 * j + 2 * tig;
            float f0 = c[i][j][0] * alpha, f1 = c[i][j][1] * alpha;
            float f2 = c[i][j][2] * alpha, f3 = c[i][j][3] * alpha;
            if (ROUND) { f0 = rna(f0); f1 = rna(f1); f2 = rna(f2); f3 = rna(f3); }
            *(float2*)(C + (long long)rowA * N + col) = make_float2(f0, f1);
            *(float2*)(C + (long long)(rowA + 8) * N + col) = make_float2(f2, f3);
        }
    }
}

// ---------------------------------------------------------------------------
// Elementwise tf32 rounding (prep)
// ---------------------------------------------------------------------------
__global__ __launch_bounds__(256) void cvt_rna_kernel(
    const float* __restrict__ in, float* __restrict__ out)
{
    int i = (blockIdx.x * 256 + threadIdx.x) * 4;
    float4 v = *(const float4*)(in + i);
    v.x = rna(v.x); v.y = rna(v.y); v.z = rna(v.z); v.w = rna(v.w);
    *(float4*)(out + i) = v;
}

// out[z][c][r] = rna(in[z][r][c]); in: R x C per z slice (out stride = R)
__global__ __launch_bounds__(256) void transpose_cvt(
    const float* __restrict__ in, float* __restrict__ out,
    int R, int Ccols, long long zStride)
{
    __shared__ float t[32][33];
    const float* inz  = in  + blockIdx.z * zStride;
    float*       outz = out + blockIdx.z * zStride;
    const int r0 = blockIdx.y * 32;
    const int c0 = blockIdx.x * 32;
    const int tx = threadIdx.x & 31;
    const int ty = threadIdx.x >> 5;   // 0..7
#pragma unroll
    for (int k = 0; k < 4; k++)
        t[ty + k * 8][tx] = inz[(long long)(r0 + ty + k * 8) * Ccols + c0 + tx];
    __syncthreads();
#pragma unroll
    for (int k = 0; k < 4; k++)
        outz[(long long)(c0 + ty + k * 8) * R + r0 + tx] = rna(t[tx][ty + k * 8]);
}

// ---------------------------------------------------------------------------
// Row softmax over 2048 columns; float4 I/O; writes tf32-rounded probabilities
// ---------------------------------------------------------------------------
__global__ __launch_bounds__(256) void softmax2048(float* __restrict__ S)
{
    float4* row4 = (float4*)(S + (long long)blockIdx.x * SEQ);
    const int tid = threadIdx.x;

    float4 va = row4[tid];
    float4 vb = row4[tid + 256];
    float x[8] = {va.x, va.y, va.z, va.w, vb.x, vb.y, vb.z, vb.w};

    float m = x[0];
#pragma unroll
    for (int i = 1; i < 8; i++) m = fmaxf(m, x[i]);
#pragma unroll
    for (int o = 16; o > 0; o >>= 1)
        m = fmaxf(m, __shfl_xor_sync(0xffffffffu, m, o));

    __shared__ float red[8];
    if ((tid & 31) == 0) red[tid >> 5] = m;
    __syncthreads();
    float mAll = red[0];
#pragma unroll
    for (int i = 1; i < 8; i++) mAll = fmaxf(mAll, red[i]);
    __syncthreads();

    float s = 0.f;
#pragma unroll
    for (int i = 0; i < 8; i++) {
        x[i] = __expf(x[i] - mAll);
        s += x[i];
    }
#pragma unroll
    for (int o = 16; o > 0; o >>= 1)
        s += __shfl_xor_sync(0xffffffffu, s, o);
    if ((tid & 31) == 0) red[tid >> 5] = s;
    __syncthreads();
    float tot = 0.f;
#pragma unroll
    for (int i = 0; i < 8; i++) tot += red[i];

    const float inv = 1.f / tot;
#pragma unroll
    for (int i = 0; i < 8; i++) x[i] = rna(x[i] * inv);
    row4[tid]       = make_float4(x[0], x[1], x[2], x[3]);
    row4[tid + 256] = make_float4(x[4], x[5], x[6], x[7]);
}

// ---------------------------------------------------------------------------
// Launch
// ---------------------------------------------------------------------------
extern "C" void kernel_launch(void* const* d_in, const int* in_sizes, int n_in,
                              void* d_out, int out_size)
{
    const float* x = (const float*)d_in[0];   // [8, 2048, 768]
    const float* w = (const float*)d_in[1];   // [3, 768, 768]
    float* out     = (float*)d_out;           // [8, 2048, 768]

    float *xtf, *wt, *qkv, *vt, *sc;
    cudaGetSymbolAddress((void**)&xtf, g_xtf);
    cudaGetSymbolAddress((void**)&wt,  g_wt);
    cudaGetSymbolAddress((void**)&qkv, g_qkv);
    cudaGetSymbolAddress((void**)&vt,  g_vt);
    cudaGetSymbolAddress((void**)&sc,  g_s);

    const float INV_SCALE = 0.125f;  // 1 / sqrt(64)

    cudaFuncSetAttribute(mma_gemm<true>,
                         cudaFuncAttributeMaxDynamicSharedMemorySize, SMEM_GEMM);
    cudaFuncSetAttribute(mma_gemm<false>,
                         cudaFuncAttributeMaxDynamicSharedMemorySize, SMEM_GEMM);

    // 0) x -> tf32-rounded; W -> W^T tf32-rounded (all GEMMs are NT)
    cvt_rna_kernel<<<(BATCH * SEQ * DIM) / 1024, 256>>>(x, xtf);
    transpose_cvt<<<dim3(DIM / 32, DIM / 32, 3), 256>>>(
        w, wt, DIM, DIM, (long long)DIM * DIM);

    // 1) QKV (NT): qkv[z] = xtf @ wt[z]^T; outputs tf32-rounded
    {
        dim3 grid(DIM / BN, (BATCH * SEQ) / BM, 3);
        mma_gemm<true><<<grid, NTHREADS, SMEM_GEMM>>>(xtf, wt, qkv,
                                       BATCH * SEQ, DIM, DIM,
                                       0LL, (long long)DIM * DIM, BSD, 1.0f);
    }

    // 1b) V -> V^T per batch (rna idempotent on already-rounded values)
    transpose_cvt<<<dim3(DIM / 32, SEQ / 32, BATCH), 256>>>(
        qkv + 2 * BSD, vt, SEQ, DIM, (long long)SEQ * DIM);

    // 2) scores = Q @ K^T / 8  (NT, batched over 8)
    {
        dim3 grid(SEQ / BN, SEQ / BM, BATCH);
        mma_gemm<false><<<grid, NTHREADS, SMEM_GEMM>>>(qkv, qkv + BSD, sc,
                                      SEQ, SEQ, DIM,
                                      (long long)SEQ * DIM, (long long)SEQ * DIM,
                                      (long long)SEQ * SEQ, INV_SCALE);
    }

    // 3) softmax over last dim; writes tf32-rounded attn
    softmax2048<<<BATCH * SEQ, 256>>>(sc);

    // 4) out = attn @ (V^T)^T  (NT, batched over 8; ldmatrix both operands)
    {
        dim3 grid(DIM / BN, SEQ / BM, BATCH);
        mma_gemm<false><<<grid, NTHREADS, SMEM_GEMM>>>(sc, vt, out,
                                       SEQ, DIM, SEQ,
                                       (long long)SEQ * SEQ, (long long)DIM * SEQ,
                                       (long long)SEQ * DIM, 1.0f);
    }
}